// round 7
// baseline (speedup 1.0000x reference)
#include <cuda_runtime.h>
#include <cuda_fp16.h>

#define IN_F  1024
#define OUT_F 1024
#define NG    8
#define BATCH 8192
#define KDIM  9216

typedef unsigned int u32;
typedef unsigned long long u64;

// Device-global scratch (allocation-free contract)
__device__ __half g_Wh[(size_t)OUT_F * KDIM];   // [O][K] 18 MB, K-major (L2-resident)
__device__ __half g_Fh[(size_t)BATCH * KDIM];   // [B][K] 151 MB, K-major

// ============================================================================
// PTX helpers
// ============================================================================
__device__ __forceinline__ u32 smem_u32(const void* p) {
    u32 a;
    asm("{ .reg .u64 t; cvta.to.shared.u64 t, %1; cvt.u32.u64 %0, t; }" : "=r"(a) : "l"(p));
    return a;
}
#define CP_ASYNC16(sa, ga) \
    asm volatile("cp.async.cg.shared.global [%0], [%1], 16;" :: "r"(sa), "l"(ga))
#define CP_COMMIT() asm volatile("cp.async.commit_group;")
#define CP_WAIT1()  asm volatile("cp.async.wait_group 1;")

#define LDSM4(r, addr) \
    asm volatile("ldmatrix.sync.aligned.m8n8.x4.shared.b16 {%0,%1,%2,%3}, [%4];" \
                 : "=r"((r)[0]), "=r"((r)[1]), "=r"((r)[2]), "=r"((r)[3]) : "r"(addr))

#define MMA16816(d, a, b) \
    asm volatile("mma.sync.aligned.m16n8k16.row.col.f32.f16.f16.f32 " \
                 "{%0,%1,%2,%3}, {%4,%5,%6,%7}, {%8,%9}, {%0,%1,%2,%3};" \
                 : "+f"((d)[0]), "+f"((d)[1]), "+f"((d)[2]), "+f"((d)[3]) \
                 : "r"((a)[0]), "r"((a)[1]), "r"((a)[2]), "r"((a)[3]), \
                   "r"((b)[0]), "r"((b)[1]))

// ============================================================================
// Phase A: effective weight W[o][k] in fp16  (k = j*1024 + i)
// ============================================================================
__global__ void build_w_kernel(const float* __restrict__ scale_base,
                               const float* __restrict__ spline_weight,
                               const float* __restrict__ scale_spline) {
    int idx = blockIdx.x * blockDim.x + threadIdx.x;
    if (idx >= IN_F * OUT_F) return;
    int o = idx >> 10;
    int i = idx & 1023;

    float sb = scale_base[(size_t)i * OUT_F + o];
    float ss = scale_spline[(size_t)i * OUT_F + o];
    __half* w = g_Wh + (size_t)o * KDIM;
    w[i] = __float2half_rn(sb);

    const float4* swp = reinterpret_cast<const float4*>(spline_weight + ((size_t)o * IN_F + i) * NG);
    float4 w0 = swp[0];
    float4 w1 = swp[1];
    w[1 * 1024 + i] = __float2half_rn(w0.x * ss);
    w[2 * 1024 + i] = __float2half_rn(w0.y * ss);
    w[3 * 1024 + i] = __float2half_rn(w0.z * ss);
    w[4 * 1024 + i] = __float2half_rn(w0.w * ss);
    w[5 * 1024 + i] = __float2half_rn(w1.x * ss);
    w[6 * 1024 + i] = __float2half_rn(w1.y * ss);
    w[7 * 1024 + i] = __float2half_rn(w1.z * ss);
    w[8 * 1024 + i] = __float2half_rn(w1.w * ss);
}

// ============================================================================
// Phase B: feature matrix F[b][k] in fp16
// ============================================================================
__global__ void build_f_kernel(const float* __restrict__ x,
                               const float* __restrict__ grid,
                               const float* __restrict__ sigma_p) {
    int idx = blockIdx.x * blockDim.x + threadIdx.x;
    if (idx >= BATCH * IN_F) return;
    int b = idx >> 10;
    int i = idx & (IN_F - 1);

    float xv = x[idx];
    float inv_sigma = __fdividef(1.0f, *sigma_p);
    size_t base = (size_t)b * KDIM;

    g_Fh[base + i] = __float2half_rn(__fdividef(xv, 1.0f + __expf(-xv)));  // silu

    const float4* gp = reinterpret_cast<const float4*>(grid + (size_t)i * NG);
    float4 g0 = gp[0];
    float4 g1 = gp[1];
    float gv[NG] = {g0.x, g0.y, g0.z, g0.w, g1.x, g1.y, g1.z, g1.w};
#pragma unroll
    for (int g = 0; g < NG; g++) {
        float t = (xv - gv[g]) * inv_sigma;
        g_Fh[base + (size_t)(1 + g) * IN_F + i] = __float2half_rn(__expf(-t * t));
    }
}

// ============================================================================
// Phase C: fp16 mma.sync GEMM: C[8192,1024] = F @ W^T
//   BM=128 BN=128 BK=64, 3-stage cp.async (32KB/stage = 96KB), 128 threads,
//   4 warps in 2x2, warp tile 64x64 -> halved smem fragment traffic,
//   2 CTAs/SM -> smooth tail.
// ============================================================================
#define BM 128
#define BN 128
#define BK 64
#define NKT (KDIM / BK)           // 144
#define STG_A 16384               // BM*BK*2
#define STG_B 16384
#define STG_BYTES (STG_A + STG_B) // 32768
#define SMEM_TOTAL (3 * STG_BYTES)  // 98304

__device__ __forceinline__ void load_stage(u32 sbase, const __half* gA, const __half* gB,
                                           int kt, int lr, int lc, u32 phys) {
    const u32 sA = sbase + (u32)(kt % 3) * STG_BYTES;
    const u32 sB = sA + STG_A;
    const __half* ga = gA + (size_t)lr * KDIM + (size_t)kt * BK + lc * 8;
    const __half* gb = gB + (size_t)lr * KDIM + (size_t)kt * BK + lc * 8;
#pragma unroll
    for (int it = 0; it < 8; it++) {
        u32 off = (u32)(lr + 16 * it) * 128 + phys;
        CP_ASYNC16(sA + off, ga + (size_t)(16 * it) * KDIM);
        CP_ASYNC16(sB + off, gb + (size_t)(16 * it) * KDIM);
    }
    CP_COMMIT();
}

__global__ void __launch_bounds__(128, 2)
gemm_kernel(float* __restrict__ C) {
    extern __shared__ __align__(1024) char smem[];
    const u32 sbase = smem_u32(smem);
    const int tid = threadIdx.x;
    const int lane = tid & 31;
    const int wid = tid >> 5;
    const int wm = wid >> 1;      // 2 warps along M
    const int wn = wid & 1;       // 2 warps along N
    const int brow = blockIdx.y * BM;
    const int bcol = blockIdx.x * BN;

    const __half* gA = g_Fh + (size_t)brow * KDIM;
    const __half* gB = g_Wh + (size_t)bcol * KDIM;

    // cp.async mapping: 128 threads -> 16 rows x 8 chunks, xor swizzle
    const int lr = tid >> 3;            // 0..15
    const int lc = tid & 7;             // 0..7
    const u32 phys = (u32)((lc ^ (lr & 7)) << 4);

    float acc[4][8][4];
#pragma unroll
    for (int mi = 0; mi < 4; mi++)
#pragma unroll
        for (int ni = 0; ni < 8; ni++)
#pragma unroll
            for (int q = 0; q < 4; q++) acc[mi][ni][q] = 0.0f;

    // prologue: fill 2 stages
    load_stage(sbase, gA, gB, 0, lr, lc, phys);
    load_stage(sbase, gA, gB, 1, lr, lc, phys);

    const int j = lane >> 3;            // ldmatrix sub-matrix id
    const int i8 = lane & 7;
    const int arow_in = (j & 1) * 8 + i8;
    const int nrow_in = (j >> 1) * 8 + i8;

    for (int kt = 0; kt < NKT; kt++) {
        CP_WAIT1();
        __syncthreads();
        if (kt + 2 < NKT) load_stage(sbase, gA, gB, kt + 2, lr, lc, phys);
        const u32 sA = sbase + (u32)(kt % 3) * STG_BYTES;
        const u32 sB = sA + STG_A;

#pragma unroll
        for (int ks = 0; ks < 4; ks++) {
            u32 a[4][4];
            u32 b[8][2];
            const int cA = ks * 2 + (j >> 1);       // A: matrices 2,3 take k8-15
            const int cB = ks * 2 + (j & 1);        // B: matrices 1,3 take k8-15
#pragma unroll
            for (int mi = 0; mi < 4; mi++) {
                int ar = wm * 64 + mi * 16 + arow_in;
                LDSM4(a[mi], sA + (u32)ar * 128 + (u32)((cA ^ i8) << 4));
            }
#pragma unroll
            for (int p = 0; p < 4; p++) {
                int br = wn * 64 + p * 16 + nrow_in;
                u32 r[4];
                LDSM4(r, sB + (u32)br * 128 + (u32)((cB ^ i8) << 4));
                b[2 * p][0] = r[0];     b[2 * p][1] = r[1];
                b[2 * p + 1][0] = r[2]; b[2 * p + 1][1] = r[3];
            }
#pragma unroll
            for (int mi = 0; mi < 4; mi++)
#pragma unroll
                for (int ni = 0; ni < 8; ni++)
                    MMA16816(acc[mi][ni], a[mi], b[ni]);
        }
        __syncthreads();
    }

    // epilogue
    const int r0 = brow + wm * 64 + (lane >> 2);
    const int c0 = bcol + wn * 64 + 2 * (lane & 3);
#pragma unroll
    for (int mi = 0; mi < 4; mi++) {
#pragma unroll
        for (int ni = 0; ni < 8; ni++) {
            float* p = C + (size_t)(r0 + mi * 16) * OUT_F + c0 + ni * 8;
            *(float2*)p = make_float2(acc[mi][ni][0], acc[mi][ni][1]);
            *(float2*)(p + (size_t)8 * OUT_F) = make_float2(acc[mi][ni][2], acc[mi][ni][3]);
        }
    }
}

// ============================================================================
extern "C" void kernel_launch(void* const* d_in, const int* in_sizes, int n_in,
                              void* d_out, int out_size) {
    const float* x             = (const float*)d_in[0];
    const float* scale_base    = (const float*)d_in[1];
    const float* spline_weight = (const float*)d_in[2];
    const float* scale_spline  = (const float*)d_in[3];
    const float* grid          = (const float*)d_in[4];
    const float* sigma         = (const float*)d_in[5];
    float* out = (float*)d_out;

    static bool attr_set = false;
    if (!attr_set) {
        cudaFuncSetAttribute(gemm_kernel,
                             cudaFuncAttributeMaxDynamicSharedMemorySize, SMEM_TOTAL);
        attr_set = true;
    }

    build_w_kernel<<<(IN_F * OUT_F + 255) / 256, 256>>>(scale_base, spline_weight, scale_spline);
    build_f_kernel<<<(BATCH * IN_F + 255) / 256, 256>>>(x, grid, sigma);
    gemm_kernel<<<dim3(OUT_F / BN, BATCH / BM), 128, SMEM_TOTAL>>>(out);
}

// round 9
// speedup vs baseline: 1.4574x; 1.4574x over previous
#include <cuda_runtime.h>
#include <cuda_fp16.h>

#define IN_F  1024
#define OUT_F 1024
#define NG    8
#define BATCH 8192
#define KDIM  9216

typedef unsigned int u32;
typedef unsigned long long u64;

// Device-global scratch (allocation-free contract)
__device__ __half g_Wh[(size_t)OUT_F * KDIM];   // [O][K] 18 MB, K-major (L2-resident)
__device__ __half g_Fh[(size_t)BATCH * KDIM];   // [B][K] 151 MB, K-major

// ============================================================================
// PTX helpers
// ============================================================================
__device__ __forceinline__ u32 smem_u32(const void* p) {
    u32 a;
    asm("{ .reg .u64 t; cvta.to.shared.u64 t, %1; cvt.u32.u64 %0, t; }" : "=r"(a) : "l"(p));
    return a;
}
#define CP_ASYNC16(sa, ga) \
    asm volatile("cp.async.cg.shared.global [%0], [%1], 16;" :: "r"(sa), "l"(ga))
#define CP_COMMIT() asm volatile("cp.async.commit_group;")
#define CP_WAIT1()  asm volatile("cp.async.wait_group 1;")

#define LDSM4(r, addr) \
    asm volatile("ldmatrix.sync.aligned.m8n8.x4.shared.b16 {%0,%1,%2,%3}, [%4];" \
                 : "=r"((r)[0]), "=r"((r)[1]), "=r"((r)[2]), "=r"((r)[3]) : "r"(addr))

#define MMA16816(d, a, b) \
    asm volatile("mma.sync.aligned.m16n8k16.row.col.f32.f16.f16.f32 " \
                 "{%0,%1,%2,%3}, {%4,%5,%6,%7}, {%8,%9}, {%0,%1,%2,%3};" \
                 : "+f"((d)[0]), "+f"((d)[1]), "+f"((d)[2]), "+f"((d)[3]) \
                 : "r"((a)[0]), "r"((a)[1]), "r"((a)[2]), "r"((a)[3]), \
                   "r"((b)[0]), "r"((b)[1]))

// ============================================================================
// Phase A: effective weight W[o][k] in fp16  (k = j*1024 + i)
// ============================================================================
__global__ void build_w_kernel(const float* __restrict__ scale_base,
                               const float* __restrict__ spline_weight,
                               const float* __restrict__ scale_spline) {
    int idx = blockIdx.x * blockDim.x + threadIdx.x;
    if (idx >= IN_F * OUT_F) return;
    int o = idx >> 10;
    int i = idx & 1023;

    float sb = scale_base[(size_t)i * OUT_F + o];
    float ss = scale_spline[(size_t)i * OUT_F + o];
    __half* w = g_Wh + (size_t)o * KDIM;
    w[i] = __float2half_rn(sb);

    const float4* swp = reinterpret_cast<const float4*>(spline_weight + ((size_t)o * IN_F + i) * NG);
    float4 w0 = swp[0];
    float4 w1 = swp[1];
    w[1 * 1024 + i] = __float2half_rn(w0.x * ss);
    w[2 * 1024 + i] = __float2half_rn(w0.y * ss);
    w[3 * 1024 + i] = __float2half_rn(w0.z * ss);
    w[4 * 1024 + i] = __float2half_rn(w0.w * ss);
    w[5 * 1024 + i] = __float2half_rn(w1.x * ss);
    w[6 * 1024 + i] = __float2half_rn(w1.y * ss);
    w[7 * 1024 + i] = __float2half_rn(w1.z * ss);
    w[8 * 1024 + i] = __float2half_rn(w1.w * ss);
}

// ============================================================================
// Phase B: feature matrix F[b][k] in fp16
// ============================================================================
__global__ void build_f_kernel(const float* __restrict__ x,
                               const float* __restrict__ grid,
                               const float* __restrict__ sigma_p) {
    int idx = blockIdx.x * blockDim.x + threadIdx.x;
    if (idx >= BATCH * IN_F) return;
    int b = idx >> 10;
    int i = idx & (IN_F - 1);

    float xv = x[idx];
    float inv_sigma = __fdividef(1.0f, *sigma_p);
    size_t base = (size_t)b * KDIM;

    g_Fh[base + i] = __float2half_rn(__fdividef(xv, 1.0f + __expf(-xv)));  // silu

    const float4* gp = reinterpret_cast<const float4*>(grid + (size_t)i * NG);
    float4 g0 = gp[0];
    float4 g1 = gp[1];
    float gv[NG] = {g0.x, g0.y, g0.z, g0.w, g1.x, g1.y, g1.z, g1.w};
#pragma unroll
    for (int g = 0; g < NG; g++) {
        float t = (xv - gv[g]) * inv_sigma;
        g_Fh[base + (size_t)(1 + g) * IN_F + i] = __float2half_rn(__expf(-t * t));
    }
}

// ============================================================================
// Phase C: fp16 mma.sync GEMM: C[8192,1024] = F @ W^T
//   BM=128 BN=256 BK=64, 3-stage cp.async (48KB/stage = 144KB), 256 threads,
//   8 warps in 2Mx4N, warp tile 64x64 -> 31% crossbar slack under HMMA floor.
//   256 CTAs -> 1.73 waves.
// ============================================================================
#define BM 128
#define BN 256
#define BK 64
#define NKT (KDIM / BK)           // 144
#define STG_A 16384               // 128 rows x 128B
#define STG_B 32768               // 256 rows x 128B
#define STG_BYTES (STG_A + STG_B) // 49152
#define SMEM_TOTAL (3 * STG_BYTES)  // 147456

__device__ __forceinline__ void load_stage(u32 sbase, const __half* gA, const __half* gB,
                                           int kt, int lr, int lc, u32 phys) {
    const u32 sA = sbase + (u32)(kt % 3) * STG_BYTES;
    const u32 sB = sA + STG_A;
    const __half* ga = gA + (size_t)lr * KDIM + (size_t)kt * BK + lc * 8;
    const __half* gb = gB + (size_t)lr * KDIM + (size_t)kt * BK + lc * 8;
#pragma unroll
    for (int it = 0; it < 4; it++) {            // A: 128 rows
        u32 off = (u32)(lr + 32 * it) * 128 + phys;
        CP_ASYNC16(sA + off, ga + (size_t)(32 * it) * KDIM);
    }
#pragma unroll
    for (int it = 0; it < 8; it++) {            // B: 256 rows
        u32 off = (u32)(lr + 32 * it) * 128 + phys;
        CP_ASYNC16(sB + off, gb + (size_t)(32 * it) * KDIM);
    }
    CP_COMMIT();
}

__global__ void __launch_bounds__(256, 1)
gemm_kernel(float* __restrict__ C) {
    extern __shared__ __align__(1024) char smem[];
    const u32 sbase = smem_u32(smem);
    const int tid = threadIdx.x;
    const int lane = tid & 31;
    const int wid = tid >> 5;
    const int wm = wid & 1;       // 2 warps along M (64 rows each)
    const int wn = wid >> 1;      // 4 warps along N (64 cols each)
    const int brow = blockIdx.y * BM;
    const int bcol = blockIdx.x * BN;

    const __half* gA = g_Fh + (size_t)brow * KDIM;
    const __half* gB = g_Wh + (size_t)bcol * KDIM;

    // cp.async mapping: 256 threads -> 32 rows x 8 chunks, xor swizzle
    const int lr = tid >> 3;            // 0..31
    const int lc = tid & 7;             // 0..7
    const u32 phys = (u32)((lc ^ (lr & 7)) << 4);

    float acc[4][8][4];
#pragma unroll
    for (int mi = 0; mi < 4; mi++)
#pragma unroll
        for (int ni = 0; ni < 8; ni++)
#pragma unroll
            for (int q = 0; q < 4; q++) acc[mi][ni][q] = 0.0f;

    // prologue: fill 2 stages
    load_stage(sbase, gA, gB, 0, lr, lc, phys);
    load_stage(sbase, gA, gB, 1, lr, lc, phys);

    const int j = lane >> 3;            // ldmatrix sub-matrix id
    const int i8 = lane & 7;
    const int arow_in = (j & 1) * 8 + i8;
    const int nrow_in = (j >> 1) * 8 + i8;

    for (int kt = 0; kt < NKT; kt++) {
        CP_WAIT1();
        __syncthreads();
        if (kt + 2 < NKT) load_stage(sbase, gA, gB, kt + 2, lr, lc, phys);
        const u32 sA = sbase + (u32)(kt % 3) * STG_BYTES;
        const u32 sB = sA + STG_A;

#pragma unroll
        for (int ks = 0; ks < 4; ks++) {
            u32 a[4][4];
            u32 b[8][2];
            const int cA = ks * 2 + (j >> 1);       // A: matrices 2,3 take k8-15
            const int cB = ks * 2 + (j & 1);        // B: matrices 1,3 take k8-15
#pragma unroll
            for (int mi = 0; mi < 4; mi++) {
                int ar = wm * 64 + mi * 16 + arow_in;
                LDSM4(a[mi], sA + (u32)ar * 128 + (u32)((cA ^ i8) << 4));
            }
#pragma unroll
            for (int p = 0; p < 4; p++) {
                int br = wn * 64 + p * 16 + nrow_in;
                u32 r[4];
                LDSM4(r, sB + (u32)br * 128 + (u32)((cB ^ i8) << 4));
                b[2 * p][0] = r[0];     b[2 * p][1] = r[1];
                b[2 * p + 1][0] = r[2]; b[2 * p + 1][1] = r[3];
            }
#pragma unroll
            for (int mi = 0; mi < 4; mi++)
#pragma unroll
                for (int ni = 0; ni < 8; ni++)
                    MMA16816(acc[mi][ni], a[mi], b[ni]);
        }
    }

    // epilogue
    const int r0 = brow + wm * 64 + (lane >> 2);
    const int c0 = bcol + wn * 64 + 2 * (lane & 3);
#pragma unroll
    for (int mi = 0; mi < 4; mi++) {
#pragma unroll
        for (int ni = 0; ni < 8; ni++) {
            float* p = C + (size_t)(r0 + mi * 16) * OUT_F + c0 + ni * 8;
            *(float2*)p = make_float2(acc[mi][ni][0], acc[mi][ni][1]);
            *(float2*)(p + (size_t)8 * OUT_F) = make_float2(acc[mi][ni][2], acc[mi][ni][3]);
        }
    }
}

// ============================================================================
extern "C" void kernel_launch(void* const* d_in, const int* in_sizes, int n_in,
                              void* d_out, int out_size) {
    const float* x             = (const float*)d_in[0];
    const float* scale_base    = (const float*)d_in[1];
    const float* spline_weight = (const float*)d_in[2];
    const float* scale_spline  = (const float*)d_in[3];
    const float* grid          = (const float*)d_in[4];
    const float* sigma         = (const float*)d_in[5];
    float* out = (float*)d_out;

    static bool attr_set = false;
    if (!attr_set) {
        cudaFuncSetAttribute(gemm_kernel,
                             cudaFuncAttributeMaxDynamicSharedMemorySize, SMEM_TOTAL);
        attr_set = true;
    }

    build_w_kernel<<<(IN_F * OUT_F + 255) / 256, 256>>>(scale_base, spline_weight, scale_spline);
    build_f_kernel<<<(BATCH * IN_F + 255) / 256, 256>>>(x, grid, sigma);
    gemm_kernel<<<dim3(OUT_F / BN, BATCH / BM), 256, SMEM_TOTAL>>>(out);
}

// round 11
// speedup vs baseline: 1.6251x; 1.1151x over previous
#include <cuda_runtime.h>
#include <cuda_fp16.h>
#include <cuda.h>

#define IN_F  1024
#define OUT_F 1024
#define NG    8
#define BATCH 8192
#define KDIM  9216

typedef unsigned int u32;
typedef unsigned long long u64;

// Device-global scratch (allocation-free contract)
__device__ __half g_Wh[(size_t)OUT_F * KDIM];   // [O][K] 18 MB, K-major (L2-resident)
__device__ __half g_Fh[(size_t)BATCH * KDIM];   // [B][K] 151 MB, K-major

// ============================================================================
// PTX helpers
// ============================================================================
__device__ __forceinline__ u32 smem_u32(const void* p) {
    u32 a;
    asm("{ .reg .u64 t; cvta.to.shared.u64 t, %1; cvt.u32.u64 %0, t; }" : "=r"(a) : "l"(p));
    return a;
}

#define MBAR_INIT(a, n) \
    asm volatile("mbarrier.init.shared.b64 [%0], %1;" :: "r"(a), "r"(n) : "memory")
#define MBAR_EXPECT_TX(a, b) \
    asm volatile("mbarrier.arrive.expect_tx.shared.b64 _, [%0], %1;" :: "r"(a), "r"(b) : "memory")

__device__ __forceinline__ void mbar_wait(u32 mbar, u32 parity) {
    asm volatile(
        "{\n\t.reg .pred P;\n\t"
        "W%=:\n\t"
        "mbarrier.try_wait.parity.acquire.cta.shared::cta.b64 P, [%0], %1, 0x989680;\n\t"
        "@P bra.uni D%=;\n\t"
        "bra.uni W%=;\n\t"
        "D%=:\n\t}"
        :: "r"(mbar), "r"(parity) : "memory");
}

__device__ __forceinline__ void tma_load(u32 dst, const CUtensorMap* m, int cx, int cy, u32 mbar) {
    asm volatile(
        "cp.async.bulk.tensor.3d.shared::cta.global.tile.mbarrier::complete_tx::bytes "
        "[%0], [%1, {%2, %3, %4}], [%5];"
        :: "r"(dst), "l"(m), "r"(cx), "r"(cy), "r"(0), "r"(mbar) : "memory");
}

#define LDSM4(r, addr) \
    asm volatile("ldmatrix.sync.aligned.m8n8.x4.shared.b16 {%0,%1,%2,%3}, [%4];" \
                 : "=r"((r)[0]), "=r"((r)[1]), "=r"((r)[2]), "=r"((r)[3]) : "r"(addr))

#define MMA16816(d, a, b) \
    asm volatile("mma.sync.aligned.m16n8k16.row.col.f32.f16.f16.f32 " \
                 "{%0,%1,%2,%3}, {%4,%5,%6,%7}, {%8,%9}, {%0,%1,%2,%3};" \
                 : "+f"((d)[0]), "+f"((d)[1]), "+f"((d)[2]), "+f"((d)[3]) \
                 : "r"((a)[0]), "r"((a)[1]), "r"((a)[2]), "r"((a)[3]), \
                   "r"((b)[0]), "r"((b)[1]))

// ============================================================================
// Phase A: effective weight W[o][k] in fp16  (k = j*1024 + i)
// ============================================================================
__global__ void build_w_kernel(const float* __restrict__ scale_base,
                               const float* __restrict__ spline_weight,
                               const float* __restrict__ scale_spline) {
    int idx = blockIdx.x * blockDim.x + threadIdx.x;
    if (idx >= IN_F * OUT_F) return;
    int o = idx >> 10;
    int i = idx & 1023;

    float sb = scale_base[(size_t)i * OUT_F + o];
    float ss = scale_spline[(size_t)i * OUT_F + o];
    __half* w = g_Wh + (size_t)o * KDIM;
    w[i] = __float2half_rn(sb);

    const float4* swp = reinterpret_cast<const float4*>(spline_weight + ((size_t)o * IN_F + i) * NG);
    float4 w0 = swp[0];
    float4 w1 = swp[1];
    w[1 * 1024 + i] = __float2half_rn(w0.x * ss);
    w[2 * 1024 + i] = __float2half_rn(w0.y * ss);
    w[3 * 1024 + i] = __float2half_rn(w0.z * ss);
    w[4 * 1024 + i] = __float2half_rn(w0.w * ss);
    w[5 * 1024 + i] = __float2half_rn(w1.x * ss);
    w[6 * 1024 + i] = __float2half_rn(w1.y * ss);
    w[7 * 1024 + i] = __float2half_rn(w1.z * ss);
    w[8 * 1024 + i] = __float2half_rn(w1.w * ss);
}

// ============================================================================
// Phase B: feature matrix F[b][k] in fp16
// ============================================================================
__global__ void build_f_kernel(const float* __restrict__ x,
                               const float* __restrict__ grid,
                               const float* __restrict__ sigma_p) {
    int idx = blockIdx.x * blockDim.x + threadIdx.x;
    if (idx >= BATCH * IN_F) return;
    int b = idx >> 10;
    int i = idx & (IN_F - 1);

    float xv = x[idx];
    float inv_sigma = __fdividef(1.0f, *sigma_p);
    size_t base = (size_t)b * KDIM;

    g_Fh[base + i] = __float2half_rn(__fdividef(xv, 1.0f + __expf(-xv)));  // silu

    const float4* gp = reinterpret_cast<const float4*>(grid + (size_t)i * NG);
    float4 g0 = gp[0];
    float4 g1 = gp[1];
    float gv[NG] = {g0.x, g0.y, g0.z, g0.w, g1.x, g1.y, g1.z, g1.w};
#pragma unroll
    for (int g = 0; g < NG; g++) {
        float t = (xv - gv[g]) * inv_sigma;
        g_Fh[base + (size_t)(1 + g) * IN_F + i] = __float2half_rn(__expf(-t * t));
    }
}

// ============================================================================
// Phase C: fp16 mma.sync GEMM with TMA fills: C[8192,1024] = F @ W^T
//   BM=128 BN=256 BK=64, 4-stage TMA pipeline (48KB/stage), 256 threads,
//   8 warps 2Mx4N, warp tile 64x64. TMA removes the cp.async issue cost
//   that bound R4-R8 at ~0.9 cyc per 16B op.
// ============================================================================
#define BM 128
#define BN 256
#define BK 64
#define NKT (KDIM / BK)           // 144
#define NSTG 4
#define STG_A 16384               // 128 rows x 128B
#define STG_B 32768               // 256 rows x 128B
#define STG_BYTES (STG_A + STG_B) // 49152
#define SM_STAGE0 1024
#define SMEM_TOTAL (SM_STAGE0 + NSTG * STG_BYTES)  // 197632

__global__ void __launch_bounds__(256, 1)
gemm_kernel(const __grid_constant__ CUtensorMap tma_a,
            const __grid_constant__ CUtensorMap tma_b,
            float* __restrict__ C) {
    extern __shared__ __align__(1024) char smem[];
    const u32 sbase = smem_u32(smem);
    const int tid = threadIdx.x;
    const int lane = tid & 31;
    const int wid = tid >> 5;
    const int wm = wid & 1;       // 2 warps along M (64 rows each)
    const int wn = wid >> 1;      // 4 warps along N (64 cols each)
    const int brow = blockIdx.y * BM;
    const int bcol = blockIdx.x * BN;

    // full barriers: one per stage, at sbase + s*8
    if (tid == 0) {
#pragma unroll
        for (int s = 0; s < NSTG; s++) MBAR_INIT(sbase + s * 8, 1);
    }
    __syncthreads();

    // prologue: issue stages 0..2
    if (tid == 0) {
#pragma unroll
        for (int kt = 0; kt < NSTG - 1; kt++) {
            const u32 full = sbase + (kt & 3) * 8;
            const u32 sA = sbase + SM_STAGE0 + (kt & 3) * STG_BYTES;
            MBAR_EXPECT_TX(full, STG_BYTES);
            tma_load(sA, &tma_a, kt * BK, brow, full);
            tma_load(sA + STG_A, &tma_b, kt * BK, bcol, full);
        }
    }

    float acc[4][8][4];
#pragma unroll
    for (int mi = 0; mi < 4; mi++)
#pragma unroll
        for (int ni = 0; ni < 8; ni++)
#pragma unroll
            for (int q = 0; q < 4; q++) acc[mi][ni][q] = 0.0f;

    const int j = lane >> 3;            // ldmatrix sub-matrix id
    const int i8 = lane & 7;
    const int arow_in = (j & 1) * 8 + i8;
    const int nrow_in = (j >> 1) * 8 + i8;

    for (int kt = 0; kt < NKT; kt++) {
        // all threads done reading stage (kt-1)&3 -> safe to overwrite with kt+3
        __syncthreads();
        if (tid == 0 && kt + NSTG - 1 < NKT) {
            const int kn = kt + NSTG - 1;
            const u32 full = sbase + (kn & 3) * 8;
            const u32 sAn = sbase + SM_STAGE0 + (kn & 3) * STG_BYTES;
            MBAR_EXPECT_TX(full, STG_BYTES);
            tma_load(sAn, &tma_a, kn * BK, brow, full);
            tma_load(sAn + STG_A, &tma_b, kn * BK, bcol, full);
        }
        mbar_wait(sbase + (kt & 3) * 8, (kt >> 2) & 1);

        const u32 sA = sbase + SM_STAGE0 + (kt & 3) * STG_BYTES;
        const u32 sB = sA + STG_A;

#pragma unroll
        for (int ks = 0; ks < 4; ks++) {
            u32 a[4][4];
            u32 b[8][2];
            const int cA = ks * 2 + (j >> 1);       // A: matrices 2,3 take k8-15
            const int cB = ks * 2 + (j & 1);        // B: matrices 1,3 take k8-15
#pragma unroll
            for (int mi = 0; mi < 4; mi++) {
                int ar = wm * 64 + mi * 16 + arow_in;
                LDSM4(a[mi], sA + (u32)ar * 128 + (u32)((cA ^ i8) << 4));
            }
#pragma unroll
            for (int p = 0; p < 4; p++) {
                int br = wn * 64 + p * 16 + nrow_in;
                u32 r[4];
                LDSM4(r, sB + (u32)br * 128 + (u32)((cB ^ i8) << 4));
                b[2 * p][0] = r[0];     b[2 * p][1] = r[1];
                b[2 * p + 1][0] = r[2]; b[2 * p + 1][1] = r[3];
            }
#pragma unroll
            for (int mi = 0; mi < 4; mi++)
#pragma unroll
                for (int ni = 0; ni < 8; ni++)
                    MMA16816(acc[mi][ni], a[mi], b[ni]);
        }
    }

    // epilogue
    const int r0 = brow + wm * 64 + (lane >> 2);
    const int c0 = bcol + wn * 64 + 2 * (lane & 3);
#pragma unroll
    for (int mi = 0; mi < 4; mi++) {
#pragma unroll
        for (int ni = 0; ni < 8; ni++) {
            float* p = C + (size_t)(r0 + mi * 16) * OUT_F + c0 + ni * 8;
            *(float2*)p = make_float2(acc[mi][ni][0], acc[mi][ni][1]);
            *(float2*)(p + (size_t)8 * OUT_F) = make_float2(acc[mi][ni][2], acc[mi][ni][3]);
        }
    }
}

// ============================================================================
// Host side
// ============================================================================
typedef CUresult (*EncodeFn)(CUtensorMap*, CUtensorMapDataType, cuuint32_t, void*,
                             const cuuint64_t*, const cuuint64_t*, const cuuint32_t*,
                             const cuuint32_t*, CUtensorMapInterleave, CUtensorMapSwizzle,
                             CUtensorMapL2promotion, CUtensorMapFloatOOBfill);

static void encode_map(EncodeFn fn, CUtensorMap* m, void* ptr, cuuint64_t rows, cuuint32_t box_rows) {
    cuuint64_t dims[3]    = {KDIM, rows, 1};
    cuuint64_t strides[2] = {(cuuint64_t)KDIM * 2, (cuuint64_t)KDIM * 2 * rows};
    cuuint32_t box[3]     = {BK, box_rows, 1};     // 64 fp16 = 128B (SW128 atom)
    cuuint32_t estr[3]    = {1, 1, 1};
    fn(m, CU_TENSOR_MAP_DATA_TYPE_FLOAT16, 3, ptr, dims, strides, box, estr,
       CU_TENSOR_MAP_INTERLEAVE_NONE, CU_TENSOR_MAP_SWIZZLE_128B,
       CU_TENSOR_MAP_L2_PROMOTION_L2_128B, CU_TENSOR_MAP_FLOAT_OOB_FILL_NONE);
}

extern "C" void kernel_launch(void* const* d_in, const int* in_sizes, int n_in,
                              void* d_out, int out_size) {
    const float* x             = (const float*)d_in[0];
    const float* scale_base    = (const float*)d_in[1];
    const float* spline_weight = (const float*)d_in[2];
    const float* scale_spline  = (const float*)d_in[3];
    const float* grid          = (const float*)d_in[4];
    const float* sigma         = (const float*)d_in[5];
    float* out = (float*)d_out;

    static EncodeFn enc = nullptr;
    if (!enc) {
        void* sym = nullptr;
        cudaDriverEntryPointQueryResult st;
        cudaGetDriverEntryPoint("cuTensorMapEncodeTiled", &sym, cudaEnableDefault, &st);
        enc = (EncodeFn)sym;
    }
    void* pF = nullptr; void* pW = nullptr;
    cudaGetSymbolAddress(&pF, g_Fh);
    cudaGetSymbolAddress(&pW, g_Wh);

    CUtensorMap map_a, map_b;
    encode_map(enc, &map_a, pF, BATCH, 128);   // A: 128-row boxes
    encode_map(enc, &map_b, pW, OUT_F, 256);   // B: 256-row boxes

    static bool attr_set = false;
    if (!attr_set) {
        cudaFuncSetAttribute(gemm_kernel,
                             cudaFuncAttributeMaxDynamicSharedMemorySize, SMEM_TOTAL);
        attr_set = true;
    }

    build_w_kernel<<<(IN_F * OUT_F + 255) / 256, 256>>>(scale_base, spline_weight, scale_spline);
    build_f_kernel<<<(BATCH * IN_F + 255) / 256, 256>>>(x, grid, sigma);
    gemm_kernel<<<dim3(OUT_F / BN, BATCH / BM), 256, SMEM_TOTAL>>>(map_a, map_b, out);
}

// round 13
// speedup vs baseline: 1.6620x; 1.0227x over previous
#include <cuda_runtime.h>
#include <cuda_fp16.h>
#include <cuda.h>

#define IN_F  1024
#define OUT_F 1024
#define NG    8
#define BATCH 8192
#define KDIM  9216

typedef unsigned int u32;
typedef unsigned long long u64;

// Device-global scratch (allocation-free contract)
__device__ __half g_Wh[(size_t)OUT_F * KDIM];   // [O][K] 18 MB, K-major (L2-resident)
__device__ __half g_Fh[(size_t)BATCH * KDIM];   // [B][K] 151 MB, K-major

// ============================================================================
// PTX helpers
// ============================================================================
__device__ __forceinline__ u32 smem_u32(const void* p) {
    u32 a;
    asm("{ .reg .u64 t; cvta.to.shared.u64 t, %1; cvt.u32.u64 %0, t; }" : "=r"(a) : "l"(p));
    return a;
}

#define MBAR_INIT(a, n) \
    asm volatile("mbarrier.init.shared.b64 [%0], %1;" :: "r"(a), "r"(n) : "memory")
#define MBAR_EXPECT_TX(a, b) \
    asm volatile("mbarrier.arrive.expect_tx.shared.b64 _, [%0], %1;" :: "r"(a), "r"(b) : "memory")

__device__ __forceinline__ void mbar_wait(u32 mbar, u32 parity) {
    asm volatile(
        "{\n\t.reg .pred P;\n\t"
        "W%=:\n\t"
        "mbarrier.try_wait.parity.acquire.cta.shared::cta.b64 P, [%0], %1, 0x989680;\n\t"
        "@P bra.uni D%=;\n\t"
        "bra.uni W%=;\n\t"
        "D%=:\n\t}"
        :: "r"(mbar), "r"(parity) : "memory");
}

__device__ __forceinline__ void tma_load(u32 dst, const CUtensorMap* m, int cx, int cy, u32 mbar) {
    asm volatile(
        "cp.async.bulk.tensor.3d.shared::cta.global.tile.mbarrier::complete_tx::bytes "
        "[%0], [%1, {%2, %3, %4}], [%5];"
        :: "r"(dst), "l"(m), "r"(cx), "r"(cy), "r"(0), "r"(mbar) : "memory");
}

#define LDSM4(r, addr) \
    asm volatile("ldmatrix.sync.aligned.m8n8.x4.shared.b16 {%0,%1,%2,%3}, [%4];" \
                 : "=r"((r)[0]), "=r"((r)[1]), "=r"((r)[2]), "=r"((r)[3]) : "r"(addr))

#define MMA16816(d, a, b) \
    asm volatile("mma.sync.aligned.m16n8k16.row.col.f32.f16.f16.f32 " \
                 "{%0,%1,%2,%3}, {%4,%5,%6,%7}, {%8,%9}, {%0,%1,%2,%3};" \
                 : "+f"((d)[0]), "+f"((d)[1]), "+f"((d)[2]), "+f"((d)[3]) \
                 : "r"((a)[0]), "r"((a)[1]), "r"((a)[2]), "r"((a)[3]), \
                   "r"((b)[0]), "r"((b)[1]))

// ============================================================================
// Phase A: effective weight W[o][k] in fp16  (k = j*1024 + i)
// ============================================================================
__global__ void build_w_kernel(const float* __restrict__ scale_base,
                               const float* __restrict__ spline_weight,
                               const float* __restrict__ scale_spline) {
    int idx = blockIdx.x * blockDim.x + threadIdx.x;
    if (idx >= IN_F * OUT_F) return;
    int o = idx >> 10;
    int i = idx & 1023;

    float sb = scale_base[(size_t)i * OUT_F + o];
    float ss = scale_spline[(size_t)i * OUT_F + o];
    __half* w = g_Wh + (size_t)o * KDIM;
    w[i] = __float2half_rn(sb);

    const float4* swp = reinterpret_cast<const float4*>(spline_weight + ((size_t)o * IN_F + i) * NG);
    float4 w0 = swp[0];
    float4 w1 = swp[1];
    w[1 * 1024 + i] = __float2half_rn(w0.x * ss);
    w[2 * 1024 + i] = __float2half_rn(w0.y * ss);
    w[3 * 1024 + i] = __float2half_rn(w0.z * ss);
    w[4 * 1024 + i] = __float2half_rn(w0.w * ss);
    w[5 * 1024 + i] = __float2half_rn(w1.x * ss);
    w[6 * 1024 + i] = __float2half_rn(w1.y * ss);
    w[7 * 1024 + i] = __float2half_rn(w1.z * ss);
    w[8 * 1024 + i] = __float2half_rn(w1.w * ss);
}

// ============================================================================
// Phase B: feature matrix F[b][k] in fp16
// ============================================================================
__global__ void build_f_kernel(const float* __restrict__ x,
                               const float* __restrict__ grid,
                               const float* __restrict__ sigma_p) {
    int idx = blockIdx.x * blockDim.x + threadIdx.x;
    if (idx >= BATCH * IN_F) return;
    int b = idx >> 10;
    int i = idx & (IN_F - 1);

    float xv = x[idx];
    float inv_sigma = __fdividef(1.0f, *sigma_p);
    size_t base = (size_t)b * KDIM;

    g_Fh[base + i] = __float2half_rn(__fdividef(xv, 1.0f + __expf(-xv)));  // silu

    const float4* gp = reinterpret_cast<const float4*>(grid + (size_t)i * NG);
    float4 g0 = gp[0];
    float4 g1 = gp[1];
    float gv[NG] = {g0.x, g0.y, g0.z, g0.w, g1.x, g1.y, g1.z, g1.w};
#pragma unroll
    for (int g = 0; g < NG; g++) {
        float t = (xv - gv[g]) * inv_sigma;
        g_Fh[base + (size_t)(1 + g) * IN_F + i] = __float2half_rn(__expf(-t * t));
    }
}

// ============================================================================
// Phase C: fp16 mma.sync GEMM, TMA fills, register-double-buffered fragments.
//   BM=128 BN=256 BK=64, 4-stage TMA (48KB/stage), 256 threads, 8 warps 2Mx4N.
// ============================================================================
#define BM 128
#define BN 256
#define BK 64
#define NKT (KDIM / BK)           // 144
#define NSTG 4
#define STG_A 16384               // 128 rows x 128B
#define STG_B 32768               // 256 rows x 128B
#define STG_BYTES (STG_A + STG_B) // 49152
#define SM_STAGE0 1024
#define SMEM_TOTAL (SM_STAGE0 + NSTG * STG_BYTES)  // 197632

struct Frag {
    u32 a[4][4];
    u32 b[8][2];
};

__device__ __forceinline__ void load_frags(Frag& f, u32 sA, u32 sB, int ks,
                                           int j, int i8, int wm, int wn,
                                           int arow_in, int nrow_in) {
    const int cA = ks * 2 + (j >> 1);
    const int cB = ks * 2 + (j & 1);
#pragma unroll
    for (int mi = 0; mi < 4; mi++) {
        int ar = wm * 64 + mi * 16 + arow_in;
        LDSM4(f.a[mi], sA + (u32)ar * 128 + (u32)((cA ^ i8) << 4));
    }
#pragma unroll
    for (int p = 0; p < 4; p++) {
        int br = wn * 64 + p * 16 + nrow_in;
        u32 r[4];
        LDSM4(r, sB + (u32)br * 128 + (u32)((cB ^ i8) << 4));
        f.b[2 * p][0] = r[0];     f.b[2 * p][1] = r[1];
        f.b[2 * p + 1][0] = r[2]; f.b[2 * p + 1][1] = r[3];
    }
}

__global__ void __launch_bounds__(256, 1)
gemm_kernel(const __grid_constant__ CUtensorMap tma_a,
            const __grid_constant__ CUtensorMap tma_b,
            float* __restrict__ C) {
    extern __shared__ __align__(1024) char smem[];
    const u32 sbase = smem_u32(smem);
    const int tid = threadIdx.x;
    const int lane = tid & 31;
    const int wid = tid >> 5;
    const int wm = wid & 1;       // 2 warps along M (64 rows each)
    const int wn = wid >> 1;      // 4 warps along N (64 cols each)
    const int brow = blockIdx.y * BM;
    const int bcol = blockIdx.x * BN;

    if (tid == 0) {
#pragma unroll
        for (int s = 0; s < NSTG; s++) MBAR_INIT(sbase + s * 8, 1);
    }
    __syncthreads();

    // prologue: fill all 4 stages
    if (tid == 0) {
#pragma unroll
        for (int kt = 0; kt < NSTG; kt++) {
            const u32 full = sbase + (kt & 3) * 8;
            const u32 sA = sbase + SM_STAGE0 + (kt & 3) * STG_BYTES;
            MBAR_EXPECT_TX(full, STG_BYTES);
            tma_load(sA, &tma_a, kt * BK, brow, full);
            tma_load(sA + STG_A, &tma_b, kt * BK, bcol, full);
        }
    }

    float acc[4][8][4];
#pragma unroll
    for (int mi = 0; mi < 4; mi++)
#pragma unroll
        for (int ni = 0; ni < 8; ni++)
#pragma unroll
            for (int q = 0; q < 4; q++) acc[mi][ni][q] = 0.0f;

    const int j = lane >> 3;
    const int i8 = lane & 7;
    const int arow_in = (j & 1) * 8 + i8;
    const int nrow_in = (j >> 1) * 8 + i8;

    Frag frag[2];

    // wait tile 0, preload frags for ks=0 into buf 0
    mbar_wait(sbase + 0, 0);
    load_frags(frag[0], sbase + SM_STAGE0, sbase + SM_STAGE0 + STG_A,
               0, j, i8, wm, wn, arow_in, nrow_in);

    for (int kt = 0; kt < NKT; kt++) {
        const u32 sA = sbase + SM_STAGE0 + (kt & 3) * STG_BYTES;
        const u32 sB = sA + STG_A;

#pragma unroll
        for (int ks = 0; ks < 4; ks++) {
            const int cur = ks & 1;
            const int nxt = cur ^ 1;

            if (ks < 3) {
                // prefetch next ks from same stage while cur's MMAs run
                load_frags(frag[nxt], sA, sB, ks + 1, j, i8, wm, wn, arow_in, nrow_in);
            } else if (kt + 1 < NKT) {
                // tile boundary: all frags of stage kt&3 are in regs.
                __syncthreads();                 // stage kt&3 drained by all warps
                if (tid == 0 && kt + NSTG < NKT) {
                    const int kn = kt + NSTG;    // refill the just-freed stage
                    const u32 full = sbase + (kn & 3) * 8;
                    const u32 sAn = sbase + SM_STAGE0 + (kn & 3) * STG_BYTES;
                    MBAR_EXPECT_TX(full, STG_BYTES);
                    tma_load(sAn, &tma_a, kn * BK, brow, full);
                    tma_load(sAn + STG_A, &tma_b, kn * BK, bcol, full);
                }
                mbar_wait(sbase + ((kt + 1) & 3) * 8, ((kt + 1) >> 2) & 1);
                const u32 sAn = sbase + SM_STAGE0 + ((kt + 1) & 3) * STG_BYTES;
                load_frags(frag[nxt], sAn, sAn + STG_A, 0, j, i8, wm, wn, arow_in, nrow_in);
            }

#pragma unroll
            for (int mi = 0; mi < 4; mi++)
#pragma unroll
                for (int ni = 0; ni < 8; ni++)
                    MMA16816(acc[mi][ni], frag[cur].a[mi], frag[cur].b[ni]);
        }
    }

    // epilogue
    const int r0 = brow + wm * 64 + (lane >> 2);
    const int c0 = bcol + wn * 64 + 2 * (lane & 3);
#pragma unroll
    for (int mi = 0; mi < 4; mi++) {
#pragma unroll
        for (int ni = 0; ni < 8; ni++) {
            float* p = C + (size_t)(r0 + mi * 16) * OUT_F + c0 + ni * 8;
            *(float2*)p = make_float2(acc[mi][ni][0], acc[mi][ni][1]);
            *(float2*)(p + (size_t)8 * OUT_F) = make_float2(acc[mi][ni][2], acc[mi][ni][3]);
        }
    }
}

// ============================================================================
// Host side
// ============================================================================
typedef CUresult (*EncodeFn)(CUtensorMap*, CUtensorMapDataType, cuuint32_t, void*,
                             const cuuint64_t*, const cuuint64_t*, const cuuint32_t*,
                             const cuuint32_t*, CUtensorMapInterleave, CUtensorMapSwizzle,
                             CUtensorMapL2promotion, CUtensorMapFloatOOBfill);

static void encode_map(EncodeFn fn, CUtensorMap* m, void* ptr, cuuint64_t rows, cuuint32_t box_rows) {
    cuuint64_t dims[3]    = {KDIM, rows, 1};
    cuuint64_t strides[2] = {(cuuint64_t)KDIM * 2, (cuuint64_t)KDIM * 2 * rows};
    cuuint32_t box[3]     = {BK, box_rows, 1};     // 64 fp16 = 128B (SW128 atom)
    cuuint32_t estr[3]    = {1, 1, 1};
    fn(m, CU_TENSOR_MAP_DATA_TYPE_FLOAT16, 3, ptr, dims, strides, box, estr,
       CU_TENSOR_MAP_INTERLEAVE_NONE, CU_TENSOR_MAP_SWIZZLE_128B,
       CU_TENSOR_MAP_L2_PROMOTION_L2_128B, CU_TENSOR_MAP_FLOAT_OOB_FILL_NONE);
}

extern "C" void kernel_launch(void* const* d_in, const int* in_sizes, int n_in,
                              void* d_out, int out_size) {
    const float* x             = (const float*)d_in[0];
    const float* scale_base    = (const float*)d_in[1];
    const float* spline_weight = (const float*)d_in[2];
    const float* scale_spline  = (const float*)d_in[3];
    const float* grid          = (const float*)d_in[4];
    const float* sigma         = (const float*)d_in[5];
    float* out = (float*)d_out;

    static EncodeFn enc = nullptr;
    if (!enc) {
        void* sym = nullptr;
        cudaDriverEntryPointQueryResult st;
        cudaGetDriverEntryPoint("cuTensorMapEncodeTiled", &sym, cudaEnableDefault, &st);
        enc = (EncodeFn)sym;
    }
    void* pF = nullptr; void* pW = nullptr;
    cudaGetSymbolAddress(&pF, g_Fh);
    cudaGetSymbolAddress(&pW, g_Wh);

    CUtensorMap map_a, map_b;
    encode_map(enc, &map_a, pF, BATCH, 128);   // A: 128-row boxes
    encode_map(enc, &map_b, pW, OUT_F, 256);   // B: 256-row boxes

    static bool attr_set = false;
    if (!attr_set) {
        cudaFuncSetAttribute(gemm_kernel,
                             cudaFuncAttributeMaxDynamicSharedMemorySize, SMEM_TOTAL);
        attr_set = true;
    }

    build_w_kernel<<<(IN_F * OUT_F + 255) / 256, 256>>>(scale_base, spline_weight, scale_spline);
    build_f_kernel<<<(BATCH * IN_F + 255) / 256, 256>>>(x, grid, sigma);
    gemm_kernel<<<dim3(OUT_F / BN, BATCH / BM), 256, SMEM_TOTAL>>>(map_a, map_b, out);
}